// round 11
// baseline (speedup 1.0000x reference)
#include <cuda_runtime.h>
#include <cuda_bf16.h>

#define SLEN 256
#define BSZ 8
#define NH 16
#define DH 64
#define IND 1024
#define ROWS (SLEN*BSZ) /* 2048 */

typedef unsigned long long ull;
typedef unsigned int uint32;

// ---- scratch (no allocs allowed -> device globals) ----
__device__ unsigned short g_ys_hi[ROWS * IND];  // scan outputs, bf16 hi (4MB)
__device__ unsigned short g_ys_lo[ROWS * IND];  // bf16 lo of residual (4MB)
__device__ unsigned short g_whi[IND * IND];     // out_w bf16 hi (2MB)
__device__ unsigned short g_wlo[IND * IND];     // out_w bf16 lo (2MB)
__device__ float g_mu[ROWS];
__device__ float g_rs[ROWS];

// ---- f32x2 helpers (sm_103a packed fp32 math, PTX-only) ----
__device__ __forceinline__ ull pack2(float lo, float hi) {
    ull r;
    asm("mov.b64 %0, {%1,%2};" : "=l"(r) : "f"(lo), "f"(hi));
    return r;
}
__device__ __forceinline__ void unpack2(ull v, float& lo, float& hi) {
    asm("mov.b64 {%0,%1}, %2;" : "=f"(lo), "=f"(hi) : "l"(v));
}
__device__ __forceinline__ ull ffma2(ull a, ull b, ull c) {
    ull d;
    asm("fma.rn.f32x2 %0, %1, %2, %3;" : "=l"(d) : "l"(a), "l"(b), "l"(c));
    return d;
}
__device__ __forceinline__ ull fmul2(ull a, ull b) {
    ull d;
    asm("mul.rn.f32x2 %0, %1, %2;" : "=l"(d) : "l"(a), "l"(b));
    return d;
}
__device__ __forceinline__ ull fadd2(ull a, ull b) {
    ull d;
    asm("add.rn.f32x2 %0, %1, %2;" : "=l"(d) : "l"(a), "l"(b));
    return d;
}
__device__ __forceinline__ float warp_sum(float v) {
    #pragma unroll
    for (int o = 16; o; o >>= 1) v += __shfl_xor_sync(0xffffffffu, v, o);
    return v;
}
// bf16 hi/lo split
__device__ __forceinline__ void split_bf16(float v, unsigned short& hi, unsigned short& lo) {
    __nv_bfloat16 hb = __float2bfloat16_rn(v);
    float rem = v - __bfloat162float(hb);
    hi = __bfloat16_as_ushort(hb);
    lo = __bfloat16_as_ushort(__float2bfloat16_rn(rem));
}
// tensor-core primitives
__device__ __forceinline__ uint32 smaddr(const void* p) {
    return (uint32)__cvta_generic_to_shared(p);
}
__device__ __forceinline__ void ldmx4(uint32* r, uint32 a) {
    asm volatile("ldmatrix.sync.aligned.m8n8.x4.shared.b16 {%0,%1,%2,%3},[%4];"
                 : "=r"(r[0]), "=r"(r[1]), "=r"(r[2]), "=r"(r[3]) : "r"(a));
}
__device__ __forceinline__ void mma16816(float* d, const uint32* a, uint32 b0, uint32 b1) {
    asm volatile(
        "mma.sync.aligned.m16n8k16.row.col.f32.bf16.bf16.f32 "
        "{%0,%1,%2,%3},{%4,%5,%6,%7},{%8,%9},{%0,%1,%2,%3};"
        : "+f"(d[0]), "+f"(d[1]), "+f"(d[2]), "+f"(d[3])
        : "r"(a[0]), "r"(a[1]), "r"(a[2]), "r"(a[3]), "r"(b0), "r"(b1));
}

// ============================================================
// Kernel 0: split out_w into bf16 hi/lo
// ============================================================
__global__ __launch_bounds__(256) void wconv_kernel(const float* __restrict__ W) {
    int idx = (blockIdx.x * 256 + threadIdx.x) * 4;
    float4 v = *(const float4*)(W + idx);
    unsigned short h0, l0, h1, l1, h2, l2, h3, l3;
    split_bf16(v.x, h0, l0); split_bf16(v.y, h1, l1);
    split_bf16(v.z, h2, l2); split_bf16(v.w, h3, l3);
    uint2 hv, lv;
    hv.x = (uint32)h0 | ((uint32)h1 << 16); hv.y = (uint32)h2 | ((uint32)h3 << 16);
    lv.x = (uint32)l0 | ((uint32)l1 << 16); lv.y = (uint32)l2 | ((uint32)l3 << 16);
    *(uint2*)(g_whi + idx) = hv;
    *(uint2*)(g_wlo + idx) = lv;
}

// ============================================================
// Kernel 1: LN row stats (fused prologue) + SRWM sequential scan.
// LAZY RANK-1 UPDATE: W registers lag one step behind. Phase A
// computes z = (stale W)x + a_prev * (k_prev . x) — the pending
// 64-op W update moves to the TOP of phase B (overlapping its
// LDS latency) and OFF the B->A critical path; next-A depends
// only on the small a/kv outputs of B. Same math (reassociation).
// ============================================================
__global__ __launch_bounds__(128, 1) void srwm_scan_kernel(
    const float* __restrict__ h,
    const float* __restrict__ Wy0, const float* __restrict__ Wq0,
    const float* __restrict__ Wk0, const float* __restrict__ wb0)
{
    const int pair = blockIdx.x;          // 0..127
    const int b  = pair >> 4;
    const int hd = pair & 15;
    const int tid  = threadIdx.x;
    const int r    = tid >> 1;            // row 0..63
    const int hf   = tid & 1;             // column half
    const int cb   = hf * 32;             // column base
    const int lane = tid & 31;
    const int warp = tid >> 5;            // 0..3

    // ---------- fused LayerNorm stats: 16 rows per CTA ----------
    {
        #pragma unroll
        for (int rr = 0; rr < 4; rr++) {
            int row = pair * 16 + warp * 4 + rr;
            const float* p = h + (size_t)row * IND + lane * 4;
            float s = 0.f, s2 = 0.f;
            #pragma unroll
            for (int i = 0; i < 8; i++) {
                float4 v = *(const float4*)(p + i * 128);
                s += (v.x + v.y) + (v.z + v.w);
                s2 = fmaf(v.x, v.x, s2); s2 = fmaf(v.y, v.y, s2);
                s2 = fmaf(v.z, v.z, s2); s2 = fmaf(v.w, v.w, s2);
            }
            s  = warp_sum(s);
            s2 = warp_sum(s2);
            if (lane == 0) {
                float mu  = s * (1.f / IND);
                float var = s2 * (1.f / IND) - mu * mu;
                g_mu[row] = mu;
                g_rs[row] = rsqrtf(var + 1e-5f);
            }
        }
    }

    __shared__ __align__(16) float xs[2][64];
    __shared__ __align__(16) float eqs[2][64], eks[2][64];
    __shared__ __align__(16) float pbp[2][8][4];   // beta partials [i][c]

    // register-resident fast weights as packed f32x2 pairs (16 each)
    ull wy2[16], wq2[16], wk2[16];
    {
        const int base = hd * 4096 + r * 64 + cb;   // 16B-aligned
        const ulonglong2* py = (const ulonglong2*)(Wy0 + base);
        const ulonglong2* pq = (const ulonglong2*)(Wq0 + base);
        const ulonglong2* pk = (const ulonglong2*)(Wk0 + base);
        #pragma unroll
        for (int j = 0; j < 8; j++) {
            ulonglong2 vy = py[j]; wy2[2*j] = vy.x; wy2[2*j+1] = vy.y;
            ulonglong2 vq = pq[j]; wq2[2*j] = vq.x; wq2[2*j+1] = vq.y;
            ulonglong2 vk = pk[j]; wk2[2*j] = vk.x; wk2[2*j+1] = vk.y;
        }
    }
    // wb: global layout (hd, j=64, c=4). Warp c owns column c.
    float wbl = wb0[hd * 256 + lane * 4 + warp];
    float wbh = wb0[hd * 256 + (lane + 32) * 4 + warp];

    const float*    hp  = h       + (size_t)b * IND + hd * 64;
    unsigned short* yhp = g_ys_hi + (size_t)b * IND + hd * 64;
    unsigned short* ylp = g_ys_lo + (size_t)b * IND + hd * 64;
    const int stride = BSZ * IND;

    // pending lazy update: a_prev (scalars + packed) and k_prev (packed cols)
    float a0p = 0.f, a1p = 0.f, a2p = 0.f;
    ull a02 = 0ull, a12 = 0ull, a22 = 0ull;
    ull kv2[16];
    #pragma unroll
    for (int j = 0; j < 16; j++) kv2[j] = 0ull;

    // preload x[0]; prefetch x[1] into regs
    if (tid < 64) xs[0][tid] = hp[tid];
    float nx = (tid < 64) ? __ldg(hp + stride + tid) : 0.f;
    __syncthreads();

    for (int t = 0; t < SLEN; ++t) {
        const int p  = t & 1;
        const int pn = p ^ 1;

        // ================= Phase A (reads xs[p]) =================
        // load x once into regs; matvec with STALE W + pending-k dot
        ull xr[16];
        #pragma unroll
        for (int j = 0; j < 8; j++) {
            xr[j]   = *(const ull*)&xs[p][cb + 2*j];
            xr[j+8] = *(const ull*)&xs[p][cb + 16 + 2*j];
        }
        ull ayA = 0ull, ayB = 0ull, aqA = 0ull, aqB = 0ull, akA = 0ull, akB = 0ull;
        ull sdA = 0ull, sdB = 0ull;
        #pragma unroll
        for (int j = 0; j < 8; j++) {
            ayA = ffma2(wy2[j], xr[j], ayA);  ayB = ffma2(wy2[j+8], xr[j+8], ayB);
            aqA = ffma2(wq2[j], xr[j], aqA);  aqB = ffma2(wq2[j+8], xr[j+8], aqB);
            akA = ffma2(wk2[j], xr[j], akA);  akB = ffma2(wk2[j+8], xr[j+8], akB);
            sdA = ffma2(kv2[j], xr[j], sdA);  sdB = ffma2(kv2[j+8], xr[j+8], sdB);
        }
        ull ay = fadd2(ayA, ayB), aq = fadd2(aqA, aqB), ak = fadd2(akA, akB);
        float zy, zq, zk, hi_;
        unpack2(ay, zy, hi_); zy += hi_;
        unpack2(aq, zq, hi_); zq += hi_;
        unpack2(ak, zk, hi_); zk += hi_;
        float sdot;
        unpack2(fadd2(sdA, sdB), sdot, hi_); sdot += hi_;
        // partner lane (same row, other half): single shfl completes row sums
        zy += __shfl_xor_sync(0xffffffffu, zy, 1);
        zq += __shfl_xor_sync(0xffffffffu, zq, 1);
        zk += __shfl_xor_sync(0xffffffffu, zk, 1);
        sdot += __shfl_xor_sync(0xffffffffu, sdot, 1);
        // lazy correction: z = (W_stale)x + a_prev * (k_prev . x)
        zy = fmaf(a0p, sdot, zy);
        zq = fmaf(a1p, sdot, zq);
        zk = fmaf(a2p, sdot, zk);

        float eq = __expf(zq), ek = __expf(zk);
        if (hf == 0) {
            eqs[p][r] = eq; eks[p][r] = ek;
            unsigned short yh, yl;
            split_bf16(zy, yh, yl);
            yhp[(size_t)t * stride + r] = yh;     // y output (pre-update Wy)
            ylp[(size_t)t * stride + r] = yl;
        }
        // beta partial: 2 shfl levels; lanes 0..7 hold 8 partials
        {
            float pb = fmaf(wbl, xs[p][lane], wbh * xs[p][lane + 32]);
            pb += __shfl_xor_sync(0xffffffffu, pb, 16);
            pb += __shfl_xor_sync(0xffffffffu, pb, 8);
            if (lane < 8) pbp[p][lane][warp] = pb;
        }
        if (tid < 64 && t + 1 < SLEN) xs[pn][tid] = nx;   // publish x[t+1]
        __syncthreads();   // single barrier per step

        // ============ Phase B (reads bank p once, writes regs only) ============
        // apply the pending rank-1 update FIRST (W_stale -> W_{t-1});
        // its issue overlaps the numerator LDS latency below.
        #pragma unroll
        for (int j = 0; j < 16; j++) {
            wy2[j] = ffma2(a02, kv2[j], wy2[j]);
            wq2[j] = ffma2(a12, kv2[j], wq2[j]);
            wk2[j] = ffma2(a22, kv2[j], wk2[j]);
        }

        if (tid < 64 && t + 2 < SLEN) nx = __ldg(hp + (size_t)(t + 2) * stride + tid);

        // single pass: load all numerator pairs into regs, sum on the fly
        ull eq2[16], ek2[16];
        ull sq2 = 0ull, sk2 = 0ull;
        #pragma unroll
        for (int j = 0; j < 8; j++) {
            eq2[j]   = *(const ull*)&eqs[p][cb + 2*j];
            ek2[j]   = *(const ull*)&eks[p][cb + 2*j];
            eq2[j+8] = *(const ull*)&eqs[p][cb + 16 + 2*j];
            ek2[j+8] = *(const ull*)&eks[p][cb + 16 + 2*j];
            sq2 = fadd2(sq2, fadd2(eq2[j], eq2[j+8]));
            sk2 = fadd2(sk2, fadd2(ek2[j], ek2[j+8]));
        }
        float stq, stk;
        unpack2(sq2, stq, hi_); stq += hi_;
        unpack2(sk2, stk, hi_); stk += hi_;
        stq += __shfl_xor_sync(0xffffffffu, stq, 1);
        stk += __shfl_xor_sync(0xffffffffu, stk, 1);
        float invq = __fdividef(1.f, stq);
        float invk = __fdividef(1.f, stk);
        ull invq2  = pack2(invq, invq);
        ull invk2  = pack2(invk, invk);
        ull ninvk2 = pack2(-invk, -invk);

        // betas from phase-A partials (packed fadd2 trees)
        ull t01 = 0ull, t23 = 0ull;
        #pragma unroll
        for (int i = 0; i < 8; i++) {
            t01 = fadd2(t01, *(const ull*)&pbp[p][i][0]);
            t23 = fadd2(t23, *(const ull*)&pbp[p][i][2]);
        }
        float pb0, pb1, pb2, pb3;
        unpack2(t01, pb0, pb1);
        unpack2(t23, pb2, pb3);
        float be0 = __fdividef(1.f, 1.f + __expf(-pb0));
        float be1 = __fdividef(1.f, 1.f + __expf(-pb1));
        float be2 = __fdividef(1.f, 1.f + __expf(-pb2));
        float be3 = __fdividef(1.f, 1.f + __expf(-pb3));

        // dv = W_{t-1} (q - k) from cached numerators (no LDS)
        ull dyA = 0ull, dyB = 0ull, dqA = 0ull, dqB = 0ull, dkA = 0ull, dkB = 0ull;
        #pragma unroll
        for (int j = 0; j < 8; j++) {
            ull mka = ffma2(ek2[j],   ninvk2, fmul2(eq2[j],   invq2));
            ull mkb = ffma2(ek2[j+8], ninvk2, fmul2(eq2[j+8], invq2));
            dyA = ffma2(wy2[j], mka, dyA);  dyB = ffma2(wy2[j+8], mkb, dyB);
            dqA = ffma2(wq2[j], mka, dqA);  dqB = ffma2(wq2[j+8], mkb, dqB);
            dkA = ffma2(wk2[j], mka, dkA);  dkB = ffma2(wk2[j+8], mkb, dkB);
        }
        ull dy2 = fadd2(dyA, dyB), dq2 = fadd2(dqA, dqB), dk2 = fadd2(dkA, dkB);
        float dy, dq, dk;
        unpack2(dy2, dy, hi_); dy += hi_;
        unpack2(dq2, dq, hi_); dq += hi_;
        unpack2(dk2, dk, hi_); dk += hi_;
        dy += __shfl_xor_sync(0xffffffffu, dy, 1);
        dq += __shfl_xor_sync(0xffffffffu, dq, 1);
        dk += __shfl_xor_sync(0xffffffffu, dk, 1);

        // NEW pending update for step t+1 (small; replaces the 64-op tail)
        a0p = be0 * dy; a1p = be1 * dq; a2p = be2 * dk;
        a02 = pack2(a0p, a0p); a12 = pack2(a1p, a1p); a22 = pack2(a2p, a2p);
        #pragma unroll
        for (int j = 0; j < 16; j++) kv2[j] = fmul2(ek2[j], invk2);

        // wb update: warp c computes dvb_c, updates its private column
        {
            float ql = eqs[p][lane]      * invq - eks[p][lane]      * invk;
            float qh = eqs[p][lane + 32] * invq - eks[p][lane + 32] * invk;
            float pd = fmaf(wbl, ql, wbh * qh);
            pd = warp_sum(pd);
            float kvl = eks[p][lane] * invk, kvh = eks[p][lane + 32] * invk;
            wbl = fmaf(be3 * kvl, pd, wbl);
            wbh = fmaf(be3 * kvh, pd, wbh);
        }
        // no trailing barrier: next phase A reads xs[pn] (covered by the
        // barrier above) and writes only smem bank pn.
    }
}

// ============================================================
// Kernel 2: out = LN(h) + ys @ out_w^T via bf16-split tensor cores.
// (exact R8 version, known-good 71us)
// ============================================================
__global__ __launch_bounds__(256, 1) void out_gemm_ln_kernel(
    const float* __restrict__ h,
    const float* __restrict__ gamma, const float* __restrict__ lbeta,
    float* __restrict__ out)
{
    __shared__ __align__(16) unsigned short sAhi[128 * 40], sAlo[128 * 40];
    __shared__ __align__(16) unsigned short sBhi[128 * 40], sBlo[128 * 40];

    const int tid  = threadIdx.x;
    const int warp = tid >> 5, lane = tid & 31;
    const int wm = (warp >> 1) * 32, wn = (warp & 1) * 64;
    const int m0 = blockIdx.y * 128, n0 = blockIdx.x * 128;

    // staging: thread -> row (0..127), k half (0 or 16)
    const int srow = tid >> 1, skg = (tid & 1) * 16;

    float acc[2][8][4];
    #pragma unroll
    for (int i = 0; i < 2; i++)
        #pragma unroll
        for (int j = 0; j < 8; j++)
            #pragma unroll
            for (int k = 0; k < 4; k++) acc[i][j][k] = 0.f;

    const unsigned short* Ah = g_ys_hi + (size_t)(m0 + srow) * IND + skg;
    const unsigned short* Al = g_ys_lo + (size_t)(m0 + srow) * IND + skg;
    const unsigned short* Bh = g_whi   + (size_t)(n0 + srow) * IND + skg;
    const unsigned short* Bl = g_wlo   + (size_t)(n0 + srow) * IND + skg;

    uint4 vah0 = *(const uint4*)(Ah),     vah1 = *(const uint4*)(Ah + 8);
    uint4 val0 = *(const uint4*)(Al),     val1 = *(const uint4*)(Al + 8);
    uint4 vbh0 = *(const uint4*)(Bh),     vbh1 = *(const uint4*)(Bh + 8);
    uint4 vbl0 = *(const uint4*)(Bl),     vbl1 = *(const uint4*)(Bl + 8);

    const int lr = lane & 15, lc = lane >> 4;
    const uint32 aHiB = smaddr(sAhi), aLoB = smaddr(sAlo);
    const uint32 bHiB = smaddr(sBhi), bLoB = smaddr(sBlo);
    const int sts = srow * 40 + skg;

    for (int kt = 0; kt < IND / 32; ++kt) {
        __syncthreads();   // previous tile fully consumed
        *(uint4*)(sAhi + sts) = vah0;  *(uint4*)(sAhi + sts + 8) = vah1;
        *(uint4*)(sAlo + sts) = val0;  *(uint4*)(sAlo + sts + 8) = val1;
        *(uint4*)(sBhi + sts) = vbh0;  *(uint4*)(sBhi + sts + 8) = vbh1;
        *(uint4*)(sBlo + sts) = vbl0;  *(uint4*)(sBlo + sts + 8) = vbl1;
        __syncthreads();
        if (kt + 1 < IND / 32) {
            const int o = (kt + 1) * 32;
            vah0 = *(const uint4*)(Ah + o); vah1 = *(const uint4*)(Ah + o + 8);
            val0 = *(const uint4*)(Al + o); val1 = *(const uint4*)(Al + o + 8);
            vbh0 = *(const uint4*)(Bh + o); vbh1 = *(const uint4*)(Bh + o + 8);
            vbl0 = *(const uint4*)(Bl + o); vbl1 = *(const uint4*)(Bl + o + 8);
        }
        #pragma unroll
        for (int ks = 0; ks < 2; ks++) {
            const int kb = ks * 32 + lc * 16;   // byte offset within row
            uint32 aH[2][4], aL[2][4];
            #pragma unroll
            for (int mt = 0; mt < 2; mt++) {
                uint32 off = (uint32)(wm + mt * 16 + lr) * 80u + kb;
                ldmx4(aH[mt], aHiB + off);
                ldmx4(aL[mt], aLoB + off);
            }
            uint32 bH[4][4], bL[4][4];
            #pragma unroll
            for (int nc = 0; nc < 4; nc++) {
                uint32 off = (uint32)(wn + nc * 16 + lr) * 80u + kb;
                ldmx4(bH[nc], bHiB + off);   // [n][k] row-major == col-major kxn
                ldmx4(bL[nc], bLoB + off);
            }
            #pragma unroll
            for (int mt = 0; mt < 2; mt++)
                #pragma unroll
                for (int nc = 0; nc < 4; nc++)
                    #pragma unroll
                    for (int hn = 0; hn < 2; hn++) {
                        float* d = acc[mt][nc * 2 + hn];
                        mma16816(d, aH[mt], bH[nc][hn], bH[nc][hn + 2]);
                        mma16816(d, aH[mt], bL[nc][hn], bL[nc][hn + 2]);
                        mma16816(d, aL[mt], bH[nc][hn], bH[nc][hn + 2]);
                    }
        }
    }

    // epilogue: out = acc + (h - mu) * rsig * gamma + beta
    const int g = lane >> 2, q = lane & 3;
    #pragma unroll
    for (int mt = 0; mt < 2; mt++) {
        int m1 = m0 + wm + mt * 16 + g;
        int m2 = m1 + 8;
        float mu1 = g_mu[m1], rs1 = g_rs[m1];
        float mu2 = g_mu[m2], rs2 = g_rs[m2];
        const float* h1 = h + (size_t)m1 * IND;
        const float* h2 = h + (size_t)m2 * IND;
        float* o1 = out + (size_t)m1 * IND;
        float* o2 = out + (size_t)m2 * IND;
        #pragma unroll
        for (int nt = 0; nt < 8; nt++) {
            int n = n0 + wn + (nt >> 1) * 16 + (nt & 1) * 8 + q * 2;
            float2 gm = *(const float2*)(gamma + n);
            float2 bt = *(const float2*)(lbeta + n);
            float2 hv1 = *(const float2*)(h1 + n);
            float2 hv2 = *(const float2*)(h2 + n);
            const float* d = acc[mt][nt];
            float2 r1, r2;
            r1.x = d[0] + (hv1.x - mu1) * rs1 * gm.x + bt.x;
            r1.y = d[1] + (hv1.y - mu1) * rs1 * gm.y + bt.y;
            r2.x = d[2] + (hv2.x - mu2) * rs2 * gm.x + bt.x;
            r2.y = d[3] + (hv2.y - mu2) * rs2 * gm.y + bt.y;
            *(float2*)(o1 + n) = r1;
            *(float2*)(o2 + n) = r2;
        }
    }
}

// ============================================================
extern "C" void kernel_launch(void* const* d_in, const int* in_sizes, int n_in,
                              void* d_out, int out_size) {
    const float* h   = (const float*)d_in[0];
    const float* Wy  = (const float*)d_in[1];
    const float* Wq  = (const float*)d_in[2];
    const float* Wk  = (const float*)d_in[3];
    const float* wb  = (const float*)d_in[4];
    const float* ow  = (const float*)d_in[5];
    const float* gam = (const float*)d_in[6];
    const float* bet = (const float*)d_in[7];
    float* out = (float*)d_out;

    wconv_kernel<<<IND * IND / 1024, 256>>>(ow);
    srwm_scan_kernel<<<BSZ * NH, 128>>>(h, Wy, Wq, Wk, wb);
    out_gemm_ln_kernel<<<dim3(IND / 128, ROWS / 128), 256>>>(h, gam, bet, out);
}

// round 12
// speedup vs baseline: 1.0318x; 1.0318x over previous
#include <cuda_runtime.h>
#include <cuda_bf16.h>

#define SLEN 256
#define BSZ 8
#define NH 16
#define DH 64
#define IND 1024
#define ROWS (SLEN*BSZ) /* 2048 */

typedef unsigned long long ull;
typedef unsigned int uint32;

// ---- scratch (no allocs allowed -> device globals) ----
__device__ unsigned short g_ys_hi[ROWS * IND];  // scan outputs, bf16 hi (4MB)
__device__ unsigned short g_ys_lo[ROWS * IND];  // bf16 lo of residual (4MB)
__device__ unsigned short g_whi[IND * IND];     // out_w bf16 hi (2MB)
__device__ unsigned short g_wlo[IND * IND];     // out_w bf16 lo (2MB)
__device__ float g_mu[ROWS];
__device__ float g_rs[ROWS];

// ---- f32x2 helpers (sm_103a packed fp32 math, PTX-only) ----
__device__ __forceinline__ ull pack2(float lo, float hi) {
    ull r;
    asm("mov.b64 %0, {%1,%2};" : "=l"(r) : "f"(lo), "f"(hi));
    return r;
}
__device__ __forceinline__ void unpack2(ull v, float& lo, float& hi) {
    asm("mov.b64 {%0,%1}, %2;" : "=f"(lo), "=f"(hi) : "l"(v));
}
__device__ __forceinline__ ull ffma2(ull a, ull b, ull c) {
    ull d;
    asm("fma.rn.f32x2 %0, %1, %2, %3;" : "=l"(d) : "l"(a), "l"(b), "l"(c));
    return d;
}
__device__ __forceinline__ ull fmul2(ull a, ull b) {
    ull d;
    asm("mul.rn.f32x2 %0, %1, %2;" : "=l"(d) : "l"(a), "l"(b));
    return d;
}
__device__ __forceinline__ ull fadd2(ull a, ull b) {
    ull d;
    asm("add.rn.f32x2 %0, %1, %2;" : "=l"(d) : "l"(a), "l"(b));
    return d;
}
__device__ __forceinline__ float warp_sum(float v) {
    #pragma unroll
    for (int o = 16; o; o >>= 1) v += __shfl_xor_sync(0xffffffffu, v, o);
    return v;
}
// bf16 hi/lo split
__device__ __forceinline__ void split_bf16(float v, unsigned short& hi, unsigned short& lo) {
    __nv_bfloat16 hb = __float2bfloat16_rn(v);
    float rem = v - __bfloat162float(hb);
    hi = __bfloat16_as_ushort(hb);
    lo = __bfloat16_as_ushort(__float2bfloat16_rn(rem));
}
// tensor-core primitives
__device__ __forceinline__ uint32 smaddr(const void* p) {
    return (uint32)__cvta_generic_to_shared(p);
}
__device__ __forceinline__ void ldmx4(uint32* r, uint32 a) {
    asm volatile("ldmatrix.sync.aligned.m8n8.x4.shared.b16 {%0,%1,%2,%3},[%4];"
                 : "=r"(r[0]), "=r"(r[1]), "=r"(r[2]), "=r"(r[3]) : "r"(a));
}
__device__ __forceinline__ void mma16816(float* d, const uint32* a, uint32 b0, uint32 b1) {
    asm volatile(
        "mma.sync.aligned.m16n8k16.row.col.f32.bf16.bf16.f32 "
        "{%0,%1,%2,%3},{%4,%5,%6,%7},{%8,%9},{%0,%1,%2,%3};"
        : "+f"(d[0]), "+f"(d[1]), "+f"(d[2]), "+f"(d[3])
        : "r"(a[0]), "r"(a[1]), "r"(a[2]), "r"(a[3]), "r"(b0), "r"(b1));
}

// ============================================================
// Kernel 0: split out_w into bf16 hi/lo
// ============================================================
__global__ __launch_bounds__(256) void wconv_kernel(const float* __restrict__ W) {
    int idx = (blockIdx.x * 256 + threadIdx.x) * 4;
    float4 v = *(const float4*)(W + idx);
    unsigned short h0, l0, h1, l1, h2, l2, h3, l3;
    split_bf16(v.x, h0, l0); split_bf16(v.y, h1, l1);
    split_bf16(v.z, h2, l2); split_bf16(v.w, h3, l3);
    uint2 hv, lv;
    hv.x = (uint32)h0 | ((uint32)h1 << 16); hv.y = (uint32)h2 | ((uint32)h3 << 16);
    lv.x = (uint32)l0 | ((uint32)l1 << 16); lv.y = (uint32)l2 | ((uint32)l3 << 16);
    *(uint2*)(g_whi + idx) = hv;
    *(uint2*)(g_wlo + idx) = lv;
}

// ============================================================
// Kernel 1: LN row stats (fused prologue) + SRWM sequential scan.
// wb[:,c] is COLUMN-SEGMENTED per thread (wbr[16] packed: warp c,
// thread covers its own 32 x-columns). beta = one extra packed-dot
// chain in phase A's matvec + 1 shfl (replaces 2-shfl+tree).
// dvb = packed dot with qmk + 1 shfl (replaces 5-shfl warp_sum).
// wb update folds into the rank-1 tail loop. No lane-indexed wb.
// ============================================================
__global__ __launch_bounds__(128, 1) void srwm_scan_kernel(
    const float* __restrict__ h,
    const float* __restrict__ Wy0, const float* __restrict__ Wq0,
    const float* __restrict__ Wk0, const float* __restrict__ wb0)
{
    const int pair = blockIdx.x;          // 0..127
    const int b  = pair >> 4;
    const int hd = pair & 15;
    const int tid  = threadIdx.x;
    const int r    = tid >> 1;            // row 0..63
    const int hf   = tid & 1;             // column half
    const int cb   = hf * 32;             // column base
    const int lane = tid & 31;
    const int warp = tid >> 5;            // 0..3 == beta channel c

    // ---------- fused LayerNorm stats: 16 rows per CTA ----------
    {
        #pragma unroll
        for (int rr = 0; rr < 4; rr++) {
            int row = pair * 16 + warp * 4 + rr;
            const float* p = h + (size_t)row * IND + lane * 4;
            float s = 0.f, s2 = 0.f;
            #pragma unroll
            for (int i = 0; i < 8; i++) {
                float4 v = *(const float4*)(p + i * 128);
                s += (v.x + v.y) + (v.z + v.w);
                s2 = fmaf(v.x, v.x, s2); s2 = fmaf(v.y, v.y, s2);
                s2 = fmaf(v.z, v.z, s2); s2 = fmaf(v.w, v.w, s2);
            }
            s  = warp_sum(s);
            s2 = warp_sum(s2);
            if (lane == 0) {
                float mu  = s * (1.f / IND);
                float var = s2 * (1.f / IND) - mu * mu;
                g_mu[row] = mu;
                g_rs[row] = rsqrtf(var + 1e-5f);
            }
        }
    }

    __shared__ __align__(16) float xs[2][64];
    __shared__ __align__(16) float eqs[2][64], eks[2][64];
    __shared__ __align__(16) float beta_s[2][4];

    // register-resident fast weights as packed f32x2 pairs (16 each)
    ull wy2[16], wq2[16], wk2[16];
    {
        const int base = hd * 4096 + r * 64 + cb;   // 16B-aligned
        const ulonglong2* py = (const ulonglong2*)(Wy0 + base);
        const ulonglong2* pq = (const ulonglong2*)(Wq0 + base);
        const ulonglong2* pk = (const ulonglong2*)(Wk0 + base);
        #pragma unroll
        for (int j = 0; j < 8; j++) {
            ulonglong2 vy = py[j]; wy2[2*j] = vy.x; wy2[2*j+1] = vy.y;
            ulonglong2 vq = pq[j]; wq2[2*j] = vq.x; wq2[2*j+1] = vq.y;
            ulonglong2 vk = pk[j]; wk2[2*j] = vk.x; wk2[2*j+1] = vk.y;
        }
    }
    // wb column c, segmented: wbr[jj] packs wb[cb+2jj][c], wb[cb+2jj+1][c]
    ull wbr[16];
    {
        const float* wbp = wb0 + hd * 256 + warp;   // (j,c) stride 4
        #pragma unroll
        for (int jj = 0; jj < 16; jj++)
            wbr[jj] = pack2(wbp[(cb + 2*jj) * 4], wbp[(cb + 2*jj + 1) * 4]);
    }

    const float*    hp  = h       + (size_t)b * IND + hd * 64;
    unsigned short* yhp = g_ys_hi + (size_t)b * IND + hd * 64;
    unsigned short* ylp = g_ys_lo + (size_t)b * IND + hd * 64;
    const int stride = BSZ * IND;

    // preload x[0]; prefetch x[1] into regs
    if (tid < 64) xs[0][tid] = hp[tid];
    float nx = (tid < 64) ? __ldg(hp + stride + tid) : 0.f;
    __syncthreads();

    for (int t = 0; t < SLEN; ++t) {
        const int p  = t & 1;
        const int pn = p ^ 1;

        // ================= Phase A (reads xs[p]) =================
        ull ayA = 0ull, ayB = 0ull, aqA = 0ull, aqB = 0ull, akA = 0ull, akB = 0ull;
        ull pbA = 0ull, pbB = 0ull;
        #pragma unroll
        for (int j = 0; j < 8; j++) {
            ull x2a = *(const ull*)&xs[p][cb + 2*j];
            ull x2b = *(const ull*)&xs[p][cb + 16 + 2*j];
            ayA = ffma2(wy2[j], x2a, ayA);  ayB = ffma2(wy2[j+8], x2b, ayB);
            aqA = ffma2(wq2[j], x2a, aqA);  aqB = ffma2(wq2[j+8], x2b, aqB);
            akA = ffma2(wk2[j], x2a, akA);  akB = ffma2(wk2[j+8], x2b, akB);
            pbA = ffma2(wbr[j], x2a, pbA);  pbB = ffma2(wbr[j+8], x2b, pbB);
        }
        ull ay = fadd2(ayA, ayB), aq = fadd2(aqA, aqB), ak = fadd2(akA, akB);
        float zy, zq, zk, hi_;
        unpack2(ay, zy, hi_); zy += hi_;
        unpack2(aq, zq, hi_); zq += hi_;
        unpack2(ak, zk, hi_); zk += hi_;
        float pb;
        unpack2(fadd2(pbA, pbB), pb, hi_); pb += hi_;
        // partner lane (same row, other half): single shfl completes sums
        zy += __shfl_xor_sync(0xffffffffu, zy, 1);
        zq += __shfl_xor_sync(0xffffffffu, zq, 1);
        zk += __shfl_xor_sync(0xffffffffu, zk, 1);
        pb += __shfl_xor_sync(0xffffffffu, pb, 1);

        float eq = __expf(zq), ek = __expf(zk);
        if (hf == 0) {
            eqs[p][r] = eq; eks[p][r] = ek;
            unsigned short yh, yl;
            split_bf16(zy, yh, yl);
            yhp[(size_t)t * stride + r] = yh;     // y output (pre-update Wy)
            ylp[(size_t)t * stride + r] = yl;
        }
        if (lane == 0) beta_s[p][warp] = __fdividef(1.f, 1.f + __expf(-pb));
        if (tid < 64 && t + 1 < SLEN) xs[pn][tid] = nx;   // publish x[t+1]
        __syncthreads();   // single barrier per step

        // ============ Phase B (reads bank p once, writes regs only) ============
        if (tid < 64 && t + 2 < SLEN) nx = __ldg(hp + (size_t)(t + 2) * stride + tid);

        // single pass: load all numerator pairs into regs, sum on the fly
        ull eq2[16], ek2[16];
        ull sq2 = 0ull, sk2 = 0ull;
        #pragma unroll
        for (int j = 0; j < 8; j++) {
            eq2[j]   = *(const ull*)&eqs[p][cb + 2*j];
            ek2[j]   = *(const ull*)&eks[p][cb + 2*j];
            eq2[j+8] = *(const ull*)&eqs[p][cb + 16 + 2*j];
            ek2[j+8] = *(const ull*)&eks[p][cb + 16 + 2*j];
            sq2 = fadd2(sq2, fadd2(eq2[j], eq2[j+8]));
            sk2 = fadd2(sk2, fadd2(ek2[j], ek2[j+8]));
        }
        float stq, stk;
        unpack2(sq2, stq, hi_); stq += hi_;
        unpack2(sk2, stk, hi_); stk += hi_;
        stq += __shfl_xor_sync(0xffffffffu, stq, 1);
        stk += __shfl_xor_sync(0xffffffffu, stk, 1);
        float invq = __fdividef(1.f, stq);
        float invk = __fdividef(1.f, stk);
        ull invq2  = pack2(invq, invq);
        ull invk2  = pack2(invk, invk);
        ull ninvk2 = pack2(-invk, -invk);

        // betas (computed in phase A, shared via smem)
        float be0 = beta_s[p][0], be1 = beta_s[p][1];
        float be2 = beta_s[p][2], be3 = beta_s[p][3];

        // dv = W (q-k) and dvb_c = wb[:,c].(q-k), all from cached numerators
        ull dyA = 0ull, dyB = 0ull, dqA = 0ull, dqB = 0ull, dkA = 0ull, dkB = 0ull;
        ull dbA = 0ull, dbB = 0ull;
        ull mk2[16];
        #pragma unroll
        for (int j = 0; j < 8; j++) {
            ull mka = ffma2(ek2[j],   ninvk2, fmul2(eq2[j],   invq2));
            ull mkb = ffma2(ek2[j+8], ninvk2, fmul2(eq2[j+8], invq2));
            mk2[j] = mka; mk2[j+8] = mkb;
            dyA = ffma2(wy2[j], mka, dyA);  dyB = ffma2(wy2[j+8], mkb, dyB);
            dqA = ffma2(wq2[j], mka, dqA);  dqB = ffma2(wq2[j+8], mkb, dqB);
            dkA = ffma2(wk2[j], mka, dkA);  dkB = ffma2(wk2[j+8], mkb, dkB);
            dbA = ffma2(wbr[j], mka, dbA);  dbB = ffma2(wbr[j+8], mkb, dbB);
        }
        ull dy2 = fadd2(dyA, dyB), dq2 = fadd2(dqA, dqB), dk2 = fadd2(dkA, dkB);
        float dy, dq, dk, pd;
        unpack2(dy2, dy, hi_); dy += hi_;
        unpack2(dq2, dq, hi_); dq += hi_;
        unpack2(dk2, dk, hi_); dk += hi_;
        unpack2(fadd2(dbA, dbB), pd, hi_); pd += hi_;
        dy += __shfl_xor_sync(0xffffffffu, dy, 1);
        dq += __shfl_xor_sync(0xffffffffu, dq, 1);
        dk += __shfl_xor_sync(0xffffffffu, dk, 1);
        pd += __shfl_xor_sync(0xffffffffu, pd, 1);

        // rank-1 updates: W += beta*dv k^T ; wb[:,c] += be3*dvb_c k
        float a0 = be0 * dy, a1 = be1 * dq, a2 = be2 * dk, a3 = be3 * pd;
        ull a02 = pack2(a0, a0), a12 = pack2(a1, a1);
        ull a22 = pack2(a2, a2), a32 = pack2(a3, a3);
        #pragma unroll
        for (int j = 0; j < 16; j++) {
            ull kv2 = fmul2(ek2[j], invk2);
            wy2[j] = ffma2(a02, kv2, wy2[j]);
            wq2[j] = ffma2(a12, kv2, wq2[j]);
            wk2[j] = ffma2(a22, kv2, wk2[j]);
            wbr[j] = ffma2(a32, kv2, wbr[j]);
        }
        // no trailing barrier: next phase A reads xs[pn] (covered by the
        // barrier above) and writes only smem bank pn.
        (void)mk2;
    }
}

// ============================================================
// Kernel 2: out = LN(h) + ys @ out_w^T via bf16-split tensor cores.
// (exact R8 version, known-good 71us)
// ============================================================
__global__ __launch_bounds__(256, 1) void out_gemm_ln_kernel(
    const float* __restrict__ h,
    const float* __restrict__ gamma, const float* __restrict__ lbeta,
    float* __restrict__ out)
{
    __shared__ __align__(16) unsigned short sAhi[128 * 40], sAlo[128 * 40];
    __shared__ __align__(16) unsigned short sBhi[128 * 40], sBlo[128 * 40];

    const int tid  = threadIdx.x;
    const int warp = tid >> 5, lane = tid & 31;
    const int wm = (warp >> 1) * 32, wn = (warp & 1) * 64;
    const int m0 = blockIdx.y * 128, n0 = blockIdx.x * 128;

    // staging: thread -> row (0..127), k half (0 or 16)
    const int srow = tid >> 1, skg = (tid & 1) * 16;

    float acc[2][8][4];
    #pragma unroll
    for (int i = 0; i < 2; i++)
        #pragma unroll
        for (int j = 0; j < 8; j++)
            #pragma unroll
            for (int k = 0; k < 4; k++) acc[i][j][k] = 0.f;

    const unsigned short* Ah = g_ys_hi + (size_t)(m0 + srow) * IND + skg;
    const unsigned short* Al = g_ys_lo + (size_t)(m0 + srow) * IND + skg;
    const unsigned short* Bh = g_whi   + (size_t)(n0 + srow) * IND + skg;
    const unsigned short* Bl = g_wlo   + (size_t)(n0 + srow) * IND + skg;

    uint4 vah0 = *(const uint4*)(Ah),     vah1 = *(const uint4*)(Ah + 8);
    uint4 val0 = *(const uint4*)(Al),     val1 = *(const uint4*)(Al + 8);
    uint4 vbh0 = *(const uint4*)(Bh),     vbh1 = *(const uint4*)(Bh + 8);
    uint4 vbl0 = *(const uint4*)(Bl),     vbl1 = *(const uint4*)(Bl + 8);

    const int lr = lane & 15, lc = lane >> 4;
    const uint32 aHiB = smaddr(sAhi), aLoB = smaddr(sAlo);
    const uint32 bHiB = smaddr(sBhi), bLoB = smaddr(sBlo);
    const int sts = srow * 40 + skg;

    for (int kt = 0; kt < IND / 32; ++kt) {
        __syncthreads();   // previous tile fully consumed
        *(uint4*)(sAhi + sts) = vah0;  *(uint4*)(sAhi + sts + 8) = vah1;
        *(uint4*)(sAlo + sts) = val0;  *(uint4*)(sAlo + sts + 8) = val1;
        *(uint4*)(sBhi + sts) = vbh0;  *(uint4*)(sBhi + sts + 8) = vbh1;
        *(uint4*)(sBlo + sts) = vbl0;  *(uint4*)(sBlo + sts + 8) = vbl1;
        __syncthreads();
        if (kt + 1 < IND / 32) {
            const int o = (kt + 1) * 32;
            vah0 = *(const uint4*)(Ah + o); vah1 = *(const uint4*)(Ah + o + 8);
            val0 = *(const uint4*)(Al + o); val1 = *(const uint4*)(Al + o + 8);
            vbh0 = *(const uint4*)(Bh + o); vbh1 = *(const uint4*)(Bh + o + 8);
            vbl0 = *(const uint4*)(Bl + o); vbl1 = *(const uint4*)(Bl + o + 8);
        }
        #pragma unroll
        for (int ks = 0; ks < 2; ks++) {
            const int kb = ks * 32 + lc * 16;   // byte offset within row
            uint32 aH[2][4], aL[2][4];
            #pragma unroll
            for (int mt = 0; mt < 2; mt++) {
                uint32 off = (uint32)(wm + mt * 16 + lr) * 80u + kb;
                ldmx4(aH[mt], aHiB + off);
                ldmx4(aL[mt], aLoB + off);
            }
            uint32 bH[4][4], bL[4][4];
            #pragma unroll
            for (int nc = 0; nc < 4; nc++) {
                uint32 off = (uint32)(wn + nc * 16 + lr) * 80u + kb;
                ldmx4(bH[nc], bHiB + off);   // [n][k] row-major == col-major kxn
                ldmx4(bL[nc], bLoB + off);
            }
            #pragma unroll
            for (int mt = 0; mt < 2; mt++)
                #pragma unroll
                for (int nc = 0; nc < 4; nc++)
                    #pragma unroll
                    for (int hn = 0; hn < 2; hn++) {
                        float* d = acc[mt][nc * 2 + hn];
                        mma16816(d, aH[mt], bH[nc][hn], bH[nc][hn + 2]);
                        mma16816(d, aH[mt], bL[nc][hn], bL[nc][hn + 2]);
                        mma16816(d, aL[mt], bH[nc][hn], bH[nc][hn + 2]);
                    }
        }
    }

    // epilogue: out = acc + (h - mu) * rsig * gamma + beta
    const int g = lane >> 2, q = lane & 3;
    #pragma unroll
    for (int mt = 0; mt < 2; mt++) {
        int m1 = m0 + wm + mt * 16 + g;
        int m2 = m1 + 8;
        float mu1 = g_mu[m1], rs1 = g_rs[m1];
        float mu2 = g_mu[m2], rs2 = g_rs[m2];
        const float* h1 = h + (size_t)m1 * IND;
        const float* h2 = h + (size_t)m2 * IND;
        float* o1 = out + (size_t)m1 * IND;
        float* o2 = out + (size_t)m2 * IND;
        #pragma unroll
        for (int nt = 0; nt < 8; nt++) {
            int n = n0 + wn + (nt >> 1) * 16 + (nt & 1) * 8 + q * 2;
            float2 gm = *(const float2*)(gamma + n);
            float2 bt = *(const float2*)(lbeta + n);
            float2 hv1 = *(const float2*)(h1 + n);
            float2 hv2 = *(const float2*)(h2 + n);
            const float* d = acc[mt][nt];
            float2 r1, r2;
            r1.x = d[0] + (hv1.x - mu1) * rs1 * gm.x + bt.x;
            r1.y = d[1] + (hv1.y - mu1) * rs1 * gm.y + bt.y;
            r2.x = d[2] + (hv2.x - mu2) * rs2 * gm.x + bt.x;
            r2.y = d[3] + (hv2.y - mu2) * rs2 * gm.y + bt.y;
            *(float2*)(o1 + n) = r1;
            *(float2*)(o2 + n) = r2;
        }
    }
}

// ============================================================
extern "C" void kernel_launch(void* const* d_in, const int* in_sizes, int n_in,
                              void* d_out, int out_size) {
    const float* h   = (const float*)d_in[0];
    const float* Wy  = (const float*)d_in[1];
    const float* Wq  = (const float*)d_in[2];
    const float* Wk  = (const float*)d_in[3];
    const float* wb  = (const float*)d_in[4];
    const float* ow  = (const float*)d_in[5];
    const float* gam = (const float*)d_in[6];
    const float* bet = (const float*)d_in[7];
    float* out = (float*)d_out;

    // scan first (profiling alignment: 4th launch == scan), wconv
    // is independent of the scan, gemm needs both.
    srwm_scan_kernel<<<BSZ * NH, 128>>>(h, Wy, Wq, Wk, wb);
    wconv_kernel<<<IND * IND / 1024, 256>>>(ow);
    out_gemm_ln_kernel<<<dim3(IND / 128, ROWS / 128), 256>>>(h, gam, bet, out);
}